// round 4
// baseline (speedup 1.0000x reference)
#include <cuda_runtime.h>

// ---------------------------------------------------------------------------
// MultiLayerAttention: out = proj( softmax_causal( (hidden@Wq^T+bq) K^T / sqrt(D) ) V )
// B=2, S=2048, H=2048, 16 Q heads, 4 KV heads (G=4), D=128.
// Reference's unscale trick cancels: effective logit scale = D^-0.5.
// ---------------------------------------------------------------------------

#define B_   2
#define S_   2048
#define H_   2048
#define NH_  16
#define NKV_ 4
#define D_   128

// Scratch (allocation-free rule: device globals)
static __device__ float g_q[(size_t)B_ * NH_ * S_ * D_];     // [b, h, s, d]  32 MB
static __device__ float g_ctx[(size_t)B_ * S_ * H_];         // [b, s, h]     32 MB

// ---------------------------------------------------------------------------
// GEMM: C[m,n] = sum_k A[m,k] * W[n,k] + bias[n]
// A: [M,K] row-major, W: [N,K] row-major.
// mode 0: write permuted into g_q layout [b, head, s, d] (qproj)
// mode 1: plain row-major write C[m*N+n]                  (outproj)
// BM=BN=128, BK=16, 256 threads, 8x8 per-thread tile. float4 global loads.
// ---------------------------------------------------------------------------
__global__ __launch_bounds__(256) void gemm_bias_kernel(
    const float* __restrict__ A, const float* __restrict__ W,
    const float* __restrict__ bias, float* __restrict__ C,
    int M, int N, int K, int mode)
{
    __shared__ float As[16][129];
    __shared__ float Bs[16][129];

    const int tid = threadIdx.x;
    const int tx = tid & 15;
    const int ty = tid >> 4;
    const int m0 = blockIdx.y * 128;
    const int n0 = blockIdx.x * 128;

    float acc[8][8];
#pragma unroll
    for (int i = 0; i < 8; i++)
#pragma unroll
        for (int j = 0; j < 8; j++) acc[i][j] = 0.0f;

    // float4 loading: 128 rows x 16 k = 2048 elems = 512 float4 per tile (A and W each).
    // 256 threads -> 2 float4 each per matrix.
    // thread t loads row lr = t >> 2, k4 = t & 3 (k offset = k4*4), rows lr and lr+64.
    const int lr = tid >> 2;
    const int k4 = (tid & 3) * 4;

    const float* Ap = A + (size_t)(m0 + lr) * K + k4;
    const float* Wp = W + (size_t)(n0 + lr) * K + k4;

    for (int kt = 0; kt < K; kt += 16) {
        float4 a0 = *(const float4*)(Ap + kt);
        float4 a1 = *(const float4*)(Ap + (size_t)64 * K + kt);
        float4 w0 = *(const float4*)(Wp + kt);
        float4 w1 = *(const float4*)(Wp + (size_t)64 * K + kt);
        __syncthreads();
        As[k4 + 0][lr] = a0.x; As[k4 + 1][lr] = a0.y; As[k4 + 2][lr] = a0.z; As[k4 + 3][lr] = a0.w;
        As[k4 + 0][lr + 64] = a1.x; As[k4 + 1][lr + 64] = a1.y; As[k4 + 2][lr + 64] = a1.z; As[k4 + 3][lr + 64] = a1.w;
        Bs[k4 + 0][lr] = w0.x; Bs[k4 + 1][lr] = w0.y; Bs[k4 + 2][lr] = w0.z; Bs[k4 + 3][lr] = w0.w;
        Bs[k4 + 0][lr + 64] = w1.x; Bs[k4 + 1][lr + 64] = w1.y; Bs[k4 + 2][lr + 64] = w1.z; Bs[k4 + 3][lr + 64] = w1.w;
        __syncthreads();
#pragma unroll
        for (int k = 0; k < 16; k++) {
            float a[8], b[8];
#pragma unroll
            for (int ii = 0; ii < 8; ii++) a[ii] = As[k][ty + ii * 16];
#pragma unroll
            for (int jj = 0; jj < 8; jj++) b[jj] = Bs[k][tx + jj * 16];
#pragma unroll
            for (int ii = 0; ii < 8; ii++)
#pragma unroll
                for (int jj = 0; jj < 8; jj++)
                    acc[ii][jj] = fmaf(a[ii], b[jj], acc[ii][jj]);
        }
    }

#pragma unroll
    for (int jj = 0; jj < 8; jj++) {
        const int n = n0 + tx + jj * 16;
        const float bv = bias[n];
#pragma unroll
        for (int ii = 0; ii < 8; ii++) {
            const int m = m0 + ty + ii * 16;
            const float v = acc[ii][jj] + bv;
            if (mode == 0) {
                // m = b*S + s ; n = head*D + d  ->  g_q[b, head, s, d]
                const int bb = m >> 11;          // S_=2048
                const int s  = m & 2047;
                const int hh = n >> 7;           // D_=128
                const int d  = n & 127;
                C[((size_t)(bb * NH_ + hh) * S_ + s) * D_ + d] = v;
            } else {
                C[(size_t)m * N + n] = v;
            }
        }
    }
}

// ---------------------------------------------------------------------------
// Flash attention (fp32, causal, GQA). 64 queries x 64 keys tiles, D=128.
// 256 threads (tx=0..15 cols, ty=0..15 rows); per-thread 4 rows (stride 16),
// 4 score cols (stride 16), 8 output d-cols (stride 16).
// smem strides chosen conflict-free: Q/K/V stride 130, P stride 65.
// ---------------------------------------------------------------------------
#define QKV_STRIDE 130
#define P_STRIDE   65
#define ATT_SMEM_BYTES ((3 * 64 * QKV_STRIDE + 64 * P_STRIDE) * 4)

__global__ __launch_bounds__(256) void attn_kernel(
    const float* __restrict__ Q,   // g_q [b, h, s, d]
    const float* __restrict__ Kg,  // [b, kv, s, d]
    const float* __restrict__ Vg,  // [b, kv, s, d]
    float* __restrict__ ctx)       // g_ctx [b, s, h]
{
    extern __shared__ float sm[];
    float* Qs = sm;
    float* Ks = Qs + 64 * QKV_STRIDE;
    float* Vs = Ks + 64 * QKV_STRIDE;
    float* Ps = Vs + 64 * QKV_STRIDE;

    const int tid = threadIdx.x;
    const int tx = tid & 15;
    const int ty = tid >> 4;
    const int qt = blockIdx.x;   // 0..31 query tiles
    const int hh = blockIdx.y;   // 0..15
    const int b  = blockIdx.z;   // 0..1
    const int kv = hh >> 2;      // G = 4
    const int q0 = qt * 64;

    const float* Qb = Q  + ((size_t)(b * NH_  + hh) * S_ + q0) * D_;
    const float* Kb = Kg + ((size_t)(b * NKV_ + kv) * S_) * D_;
    const float* Vb = Vg + ((size_t)(b * NKV_ + kv) * S_) * D_;

    // float4 tile fill indexing: 64 rows x 128 cols = 2048 float4s, 256 thr -> 8 each
    const int fr = tid >> 5;         // row base 0..7 (row = fr + it*8)
    const int fc = (tid & 31) * 4;   // col 0..124

    // load Q tile (coalesced float4)
#pragma unroll
    for (int it = 0; it < 8; it++) {
        const int r = fr + it * 8;
        float4 v = *(const float4*)(Qb + (size_t)r * D_ + fc);
        float* dst = Qs + r * QKV_STRIDE + fc;
        dst[0] = v.x; dst[1] = v.y; dst[2] = v.z; dst[3] = v.w;
    }

    float m_i[4], l_i[4], o[4][8];
#pragma unroll
    for (int ii = 0; ii < 4; ii++) {
        m_i[ii] = -1e30f;
        l_i[ii] = 0.0f;
#pragma unroll
        for (int dd = 0; dd < 8; dd++) o[ii][dd] = 0.0f;
    }

    const float SCALE = 0.08838834764831845f;  // 1/sqrt(128)

    for (int kt = 0; kt <= qt; kt++) {
        const int k0 = kt * 64;
        __syncthreads();  // protect Qs (first iter) and Ks/Vs/Ps from prior reads
#pragma unroll
        for (int it = 0; it < 8; it++) {
            const int r = fr + it * 8;
            float4 kvv = *(const float4*)(Kb + (size_t)(k0 + r) * D_ + fc);
            float4 vvv = *(const float4*)(Vb + (size_t)(k0 + r) * D_ + fc);
            float* kd = Ks + r * QKV_STRIDE + fc;
            float* vd = Vs + r * QKV_STRIDE + fc;
            kd[0] = kvv.x; kd[1] = kvv.y; kd[2] = kvv.z; kd[3] = kvv.w;
            vd[0] = vvv.x; vd[1] = vvv.y; vd[2] = vvv.z; vd[3] = vvv.w;
        }
        __syncthreads();

        // S = Q K^T (64x64 tile)
        float s[4][4];
#pragma unroll
        for (int ii = 0; ii < 4; ii++)
#pragma unroll
            for (int jj = 0; jj < 4; jj++) s[ii][jj] = 0.0f;

#pragma unroll 4
        for (int d = 0; d < 128; d++) {
            float qv[4], kvv[4];
#pragma unroll
            for (int ii = 0; ii < 4; ii++) qv[ii] = Qs[(ty + ii * 16) * QKV_STRIDE + d];
#pragma unroll
            for (int jj = 0; jj < 4; jj++) kvv[jj] = Ks[(tx + jj * 16) * QKV_STRIDE + d];
#pragma unroll
            for (int ii = 0; ii < 4; ii++)
#pragma unroll
                for (int jj = 0; jj < 4; jj++)
                    s[ii][jj] = fmaf(qv[ii], kvv[jj], s[ii][jj]);
        }

        const bool diag = (kt == qt);
#pragma unroll
        for (int ii = 0; ii < 4; ii++)
#pragma unroll
            for (int jj = 0; jj < 4; jj++) {
                s[ii][jj] *= SCALE;
                if (diag && (tx + jj * 16) > (ty + ii * 16)) s[ii][jj] = -1e30f;
            }

        // online softmax (reduce across tx lanes: lane bits 0..3)
#pragma unroll
        for (int ii = 0; ii < 4; ii++) {
            float mx = fmaxf(fmaxf(s[ii][0], s[ii][1]), fmaxf(s[ii][2], s[ii][3]));
#pragma unroll
            for (int off = 1; off < 16; off <<= 1)
                mx = fmaxf(mx, __shfl_xor_sync(0xffffffffu, mx, off));
            const float mnew = fmaxf(m_i[ii], mx);
            const float corr = __expf(m_i[ii] - mnew);
            m_i[ii] = mnew;
            float ls = 0.0f;
#pragma unroll
            for (int jj = 0; jj < 4; jj++) {
                const float p = __expf(s[ii][jj] - mnew);
                s[ii][jj] = p;
                ls += p;
            }
#pragma unroll
            for (int off = 1; off < 16; off <<= 1)
                ls += __shfl_xor_sync(0xffffffffu, ls, off);
            l_i[ii] = l_i[ii] * corr + ls;
#pragma unroll
            for (int dd = 0; dd < 8; dd++) o[ii][dd] *= corr;
        }

        // P -> smem
#pragma unroll
        for (int ii = 0; ii < 4; ii++)
#pragma unroll
            for (int jj = 0; jj < 4; jj++)
                Ps[(ty + ii * 16) * P_STRIDE + tx + jj * 16] = s[ii][jj];
        __syncthreads();

        // O += P V
#pragma unroll 4
        for (int j = 0; j < 64; j++) {
            float pv[4];
#pragma unroll
            for (int ii = 0; ii < 4; ii++) pv[ii] = Ps[(ty + ii * 16) * P_STRIDE + j];
#pragma unroll
            for (int dd = 0; dd < 8; dd++) {
                const float vvv = Vs[j * QKV_STRIDE + tx + dd * 16];
#pragma unroll
                for (int ii = 0; ii < 4; ii++)
                    o[ii][dd] = fmaf(pv[ii], vvv, o[ii][dd]);
            }
        }
    }

    // epilogue: normalize and write ctx[b, s, hh*128 + d]
#pragma unroll
    for (int ii = 0; ii < 4; ii++) {
        const float inv = 1.0f / l_i[ii];
        const int qi = q0 + ty + ii * 16;
#pragma unroll
        for (int dd = 0; dd < 8; dd++) {
            ctx[((size_t)(b * S_ + qi)) * H_ + hh * D_ + tx + dd * 16] = o[ii][dd] * inv;
        }
    }
}

// ---------------------------------------------------------------------------
extern "C" void kernel_launch(void* const* d_in, const int* in_sizes, int n_in,
                              void* d_out, int out_size)
{
    const float* hidden = (const float*)d_in[0];
    const float* key    = (const float*)d_in[1];
    const float* value  = (const float*)d_in[2];
    const float* w_q    = (const float*)d_in[3];
    const float* b_q    = (const float*)d_in[4];
    const float* w_proj = (const float*)d_in[5];
    const float* b_proj = (const float*)d_in[6];
    float* out = (float*)d_out;

    float* qbuf = nullptr;
    float* ctxbuf = nullptr;
    cudaGetSymbolAddress((void**)&qbuf, g_q);
    cudaGetSymbolAddress((void**)&ctxbuf, g_ctx);

    cudaFuncSetAttribute(attn_kernel,
                         cudaFuncAttributeMaxDynamicSharedMemorySize,
                         ATT_SMEM_BYTES);

    const int M = B_ * S_;   // 4096
    const int N = H_;        // 2048
    const int K = H_;        // 2048

    dim3 gblk(256);
    dim3 ggrid(N / 128, M / 128);

    // 1) Q projection -> g_q [b, head, s, d]
    gemm_bias_kernel<<<ggrid, gblk>>>(hidden, w_q, b_q, qbuf, M, N, K, 0);

    // 2) causal GQA attention -> g_ctx [b, s, h]
    dim3 agrid(S_ / 64, NH_, B_);
    attn_kernel<<<agrid, 256, ATT_SMEM_BYTES>>>(qbuf, key, value, ctxbuf);

    // 3) output projection -> d_out
    gemm_bias_kernel<<<ggrid, gblk>>>(ctxbuf, w_proj, b_proj, out, M, N, K, 1);
}